// round 16
// baseline (speedup 1.0000x reference)
#include <cuda_runtime.h>
#include <cuda_fp16.h>
#include <cstdint>
#include <cstddef>

// ---------------------------------------------------------------------------
// WindowAttention (Swin) on GB300 — Round 16.
// gemm1 epilogue now emits pre-split fp16 q (scaled, hi/lo), k (hi/lo), v (hi)
// directly; attention loads fp16 and skips all conversion math. Exp phase
// guarded to real rows (<49). GEMM mainloop / attention MMA phases: R15.
// ---------------------------------------------------------------------------

#define NWIN      8192
#define NTOK      49
#define DIM       384
#define NHEAD     12
#define HEADD     32
#define NW_IMG    64
#define MROWS     (NWIN * NTOK)        // 401408
#define QKV_COLS  1152
#define KG        384                  // GEMM K (plain fp16)
#define SCALE_F   0.17677669529663687f
#define EXP_SHIFT 5.545177444479562f   // 8*ln2 headroom for fp16 P
#define BM_STRIDE 50
#define BM_SLICE  3200                 // 64 rows * 50

// Device scratch
__device__ __half g_x2[(size_t)MROWS * KG];
__device__ __half g_attn2[(size_t)MROWS * KG];
__device__ __half g_wqkv2[(size_t)QKV_COLS * KG];
__device__ __half g_wproj2[(size_t)DIM * KG];
__device__ float  g_bm[(size_t)NW_IMG * NHEAD * BM_SLICE];
// pre-split qkv (fp16), each [MROWS][384]
__device__ __half g_qh[(size_t)MROWS * DIM];
__device__ __half g_ql[(size_t)MROWS * DIM];
__device__ __half g_kh[(size_t)MROWS * DIM];
__device__ __half g_kl[(size_t)MROWS * DIM];
__device__ __half g_vh[(size_t)MROWS * DIM];

// ---------------------------------------------------------------------------
// Helpers
// ---------------------------------------------------------------------------
__device__ __forceinline__ uint32_t smem_u32(const void* p) {
    uint32_t a;
    asm("{ .reg .u64 t; cvta.to.shared.u64 t, %1; cvt.u32.u64 %0, t; }"
        : "=r"(a) : "l"(p));
    return a;
}

__device__ __forceinline__ void cpa16(uint32_t dst, const void* src) {
    asm volatile("cp.async.cg.shared.global [%0], [%1], 16;"
                 :: "r"(dst), "l"(src));
}

__device__ __forceinline__ void ldsm_x4(uint32_t* r, uint32_t addr) {
    asm volatile("ldmatrix.sync.aligned.m8n8.x4.shared.b16 {%0,%1,%2,%3}, [%4];"
                 : "=r"(r[0]), "=r"(r[1]), "=r"(r[2]), "=r"(r[3])
                 : "r"(addr));
}

__device__ __forceinline__ void mma16816(float* d, const uint32_t* a,
                                         const uint32_t* b) {
    asm volatile(
        "mma.sync.aligned.m16n8k16.row.col.f32.f16.f16.f32 "
        "{%0,%1,%2,%3}, {%4,%5,%6,%7}, {%8,%9}, {%0,%1,%2,%3};"
        : "+f"(d[0]), "+f"(d[1]), "+f"(d[2]), "+f"(d[3])
        : "r"(a[0]), "r"(a[1]), "r"(a[2]), "r"(a[3]),
          "r"(b[0]), "r"(b[1]));
}

// exp(x) on the FMA pipe: 2^(x*log2e), deg-5 poly, rel err ~2.4e-6.
__device__ __forceinline__ float fast_exp(float x) {
    float t = fmaxf(x, -80.0f) * 1.442695040888963f;
    float r = rintf(t);
    float f = t - r;
    float p =             1.3333558e-3f;
    p = fmaf(p, f, 9.6181291e-3f);
    p = fmaf(p, f, 5.5504109e-2f);
    p = fmaf(p, f, 2.4022651e-1f);
    p = fmaf(p, f, 6.9314718e-1f);
    p = fmaf(p, f, 1.0f);
    int ri = (int)r;
    return __int_as_float(__float_as_int(p) + ri * 8388608);
}

// ---------------------------------------------------------------------------
// Prep kernel: fp32 [rows][384] -> fp16 [rows][384] for x, qkv_w, proj_w.
// ---------------------------------------------------------------------------
__global__ void prep_all(const float* __restrict__ x,
                         const float* __restrict__ qkv_w,
                         const float* __restrict__ proj_w,
                         __half* __restrict__ x2,
                         __half* __restrict__ wq2,
                         __half* __restrict__ wp2,
                         long t4x, long t4wq, long t4wp)
{
    long idx = (long)blockIdx.x * blockDim.x + threadIdx.x;
    const float* in;
    __half* out;
    if (idx < t4x)                    { in = x;      out = x2; }
    else if (idx < t4x + t4wq)        { idx -= t4x;  in = qkv_w; out = wq2; }
    else if (idx < t4x + t4wq + t4wp) { idx -= t4x + t4wq; in = proj_w; out = wp2; }
    else return;

    float4 v = *((const float4*)in + idx);
    __half2* o = (__half2*)out + idx * 2;
    o[0] = __halves2half2(__float2half_rn(v.x), __float2half_rn(v.y));
    o[1] = __halves2half2(__float2half_rn(v.z), __float2half_rn(v.w));
}

// bias+mask combine
__global__ void bm_prep_kernel(const float* __restrict__ rel_table,
                               const int* __restrict__ rel_idx,
                               const float* __restrict__ mask)
{
    long t = (long)blockIdx.x * blockDim.x + threadIdx.x;
    if (t >= (long)NW_IMG * NHEAD * NTOK * NTOK) return;
    int slice = (int)(t / (NTOK * NTOK));
    int idx   = (int)(t - (long)slice * (NTOK * NTOK));
    int wm    = slice / NHEAD;
    int h     = slice - wm * NHEAD;
    int i     = idx / NTOK;
    int j     = idx - i * NTOK;
    g_bm[(size_t)slice * BM_SLICE + i * BM_STRIDE + j] =
        rel_table[rel_idx[idx] * NHEAD + h] + mask[(size_t)wm * (NTOK * NTOK) + idx];
}

// ---------------------------------------------------------------------------
// HMMA GEMM (K=384). mode 0: fp32 C+bias store. mode 1: qkv split epilogue.
// ---------------------------------------------------------------------------
#define BKC       64
#define NCH       (KG / BKC)            // 6
#define TILE_BYTES 16384
#define STAGE_BYTES (2 * TILE_BYTES)
#define GSMEM     (2 * STAGE_BYTES + 128)

__global__ __launch_bounds__(256, 2)
void gemm_mma(const __half* __restrict__ A,
              const __half* __restrict__ B,
              const float* __restrict__ bias,
              float* __restrict__ C, int Nn, int mode)
{
    extern __shared__ uint8_t smem_raw[];
    const int tid  = threadIdx.x;
    const int warp = tid >> 5;
    const int lane = tid & 31;

    uint32_t sraw  = smem_u32(smem_raw);
    uint32_t sbase = (sraw + 127u) & ~127u;

    const int m0 = blockIdx.y << 7;
    const int n0 = blockIdx.x << 7;

    const char* Ag = (const char*)(A + (size_t)m0 * KG);
    const char* Bg = (const char*)(B + (size_t)n0 * KG);
    uint32_t sw[4];
    size_t   go[4];
    #pragma unroll
    for (int i = 0; i < 4; i++) {
        int u = i * 256 + tid;
        int r = u >> 3, c = u & 7;
        sw[i] = (uint32_t)(r * 128 + ((c ^ (r & 7)) << 4));
        go[i] = (size_t)r * (KG * 2) + (size_t)c * 16;
    }

    auto load_chunk = [&](int c, int s) {
        uint32_t ab = sbase + s * STAGE_BYTES;
        uint32_t bb = ab + TILE_BYTES;
        size_t koff = (size_t)c * 128;
        #pragma unroll
        for (int i = 0; i < 4; i++) {
            cpa16(ab + sw[i], Ag + go[i] + koff);
            cpa16(bb + sw[i], Bg + go[i] + koff);
        }
        asm volatile("cp.async.commit_group;" ::: "memory");
    };

    const int wm = warp & 1;
    const int wn = warp >> 1;
    const int l15 = lane & 15;
    const int lhi = lane >> 4;
    const int g8  = lane >> 3;
    const int l8  = lane & 7;

    int rA[4], rowOffA[4];
    #pragma unroll
    for (int mf = 0; mf < 4; mf++) {
        rA[mf] = wm * 64 + mf * 16 + l15;
        rowOffA[mf] = rA[mf] * 128;
    }
    int rB[2], rowOffB[2];
    #pragma unroll
    for (int p = 0; p < 2; p++) {
        rB[p] = wn * 32 + p * 16 + (g8 >> 1) * 8 + l8;
        rowOffB[p] = rB[p] * 128;
    }

    float acc[4][4][4];
    #pragma unroll
    for (int mf = 0; mf < 4; mf++)
        #pragma unroll
        for (int nf = 0; nf < 4; nf++)
            #pragma unroll
            for (int e = 0; e < 4; e++) acc[mf][nf][e] = 0.0f;

    load_chunk(0, 0);

    for (int c = 0; c < NCH; ++c) {
        if (c + 1 < NCH) {
            load_chunk(c + 1, (c + 1) & 1);
            asm volatile("cp.async.wait_group 1;" ::: "memory");
        } else {
            asm volatile("cp.async.wait_group 0;" ::: "memory");
        }
        __syncthreads();

        const uint32_t aT = sbase + (c & 1) * STAGE_BYTES;
        const uint32_t bT = aT + TILE_BYTES;

        #pragma unroll
        for (int ks = 0; ks < 4; ++ks) {
            uint32_t af[4][4];
            #pragma unroll
            for (int mf = 0; mf < 4; mf++) {
                const int c16 = ks * 2 + lhi;
                ldsm_x4(af[mf], aT + rowOffA[mf] +
                                ((c16 ^ (rA[mf] & 7)) << 4));
            }
            uint32_t bf[2][4];
            #pragma unroll
            for (int p = 0; p < 2; p++) {
                const int c16 = ks * 2 + (g8 & 1);
                ldsm_x4(bf[p], bT + rowOffB[p] +
                               ((c16 ^ (rB[p] & 7)) << 4));
            }
            #pragma unroll
            for (int mf = 0; mf < 4; mf++) {
                mma16816(acc[mf][0], af[mf], &bf[0][0]);
                mma16816(acc[mf][1], af[mf], &bf[0][2]);
                mma16816(acc[mf][2], af[mf], &bf[1][0]);
                mma16816(acc[mf][3], af[mf], &bf[1][2]);
            }
        }
        __syncthreads();
    }

    const int colBase = n0 + wn * 32 + 2 * (lane & 3);
    float2 b2[4];
    #pragma unroll
    for (int nf = 0; nf < 4; nf++)
        b2[nf] = *(const float2*)(bias + colBase + nf * 8);

    const int rowBase = m0 + wm * 64 + (lane >> 2);

    if (mode == 0) {
        #pragma unroll
        for (int mf = 0; mf < 4; mf++) {
            const int r0 = rowBase + mf * 16;
            #pragma unroll
            for (int nf = 0; nf < 4; nf++) {
                const int col = colBase + nf * 8;
                float2 v0 = make_float2(acc[mf][nf][0] + b2[nf].x,
                                        acc[mf][nf][1] + b2[nf].y);
                float2 v1 = make_float2(acc[mf][nf][2] + b2[nf].x,
                                        acc[mf][nf][3] + b2[nf].y);
                *(float2*)(C + (size_t)r0 * Nn + col)       = v0;
                *(float2*)(C + (size_t)(r0 + 8) * Nn + col) = v1;
            }
        }
    } else {
        // qkv split epilogue: region 0=q (scale+hi/lo), 1=k (hi/lo), 2=v (hi)
        const int region   = n0 / DIM;
        const int dcolBase = colBase - region * DIM;
        #pragma unroll
        for (int mf = 0; mf < 4; mf++) {
            const int r0 = rowBase + mf * 16;
            #pragma unroll
            for (int nf = 0; nf < 4; nf++) {
                const int dcol = dcolBase + nf * 8;
                float a0 = acc[mf][nf][0] + b2[nf].x;
                float a1 = acc[mf][nf][1] + b2[nf].y;
                float a2 = acc[mf][nf][2] + b2[nf].x;
                float a3 = acc[mf][nf][3] + b2[nf].y;
                const size_t o0 = (size_t)r0 * DIM + dcol;
                const size_t o1 = (size_t)(r0 + 8) * DIM + dcol;
                if (region == 0) {
                    a0 *= SCALE_F; a1 *= SCALE_F; a2 *= SCALE_F; a3 *= SCALE_F;
                    __half h0 = __float2half_rn(a0), h1 = __float2half_rn(a1);
                    __half h2 = __float2half_rn(a2), h3 = __float2half_rn(a3);
                    *(__half2*)&g_qh[o0] = __halves2half2(h0, h1);
                    *(__half2*)&g_qh[o1] = __halves2half2(h2, h3);
                    *(__half2*)&g_ql[o0] = __halves2half2(
                        __float2half_rn(a0 - __half2float(h0)),
                        __float2half_rn(a1 - __half2float(h1)));
                    *(__half2*)&g_ql[o1] = __halves2half2(
                        __float2half_rn(a2 - __half2float(h2)),
                        __float2half_rn(a3 - __half2float(h3)));
                } else if (region == 1) {
                    __half h0 = __float2half_rn(a0), h1 = __float2half_rn(a1);
                    __half h2 = __float2half_rn(a2), h3 = __float2half_rn(a3);
                    *(__half2*)&g_kh[o0] = __halves2half2(h0, h1);
                    *(__half2*)&g_kh[o1] = __halves2half2(h2, h3);
                    *(__half2*)&g_kl[o0] = __halves2half2(
                        __float2half_rn(a0 - __half2float(h0)),
                        __float2half_rn(a1 - __half2float(h1)));
                    *(__half2*)&g_kl[o1] = __halves2half2(
                        __float2half_rn(a2 - __half2float(h2)),
                        __float2half_rn(a3 - __half2float(h3)));
                } else {
                    *(__half2*)&g_vh[o0] = __halves2half2(
                        __float2half_rn(a0), __float2half_rn(a1));
                    *(__half2*)&g_vh[o1] = __halves2half2(
                        __float2half_rn(a2), __float2half_rn(a3));
                }
            }
        }
    }
}

// ---------------------------------------------------------------------------
// Tensor-core attention: grid (NWIN, NHEAD), 128 threads. fp16 pre-split
// inputs; exp phase guarded to rows < 49.
// ---------------------------------------------------------------------------
#define A_QA1 0
#define A_QA2 8192
#define A_KB  16384
#define A_PH  24576
#define A_VT  32768
#define ASMEM (36864 + 128)

__device__ __forceinline__ uint32_t tile_addr(uint32_t tile, int row, int j) {
    return tile + row * 128 + ((((j >> 3) ^ (row & 7)) << 4) | ((j & 7) * 2));
}

__global__ __launch_bounds__(128)
void attn_tc_kernel()
{
    extern __shared__ uint8_t asm_raw[];
    const int tid  = threadIdx.x;
    const int warp = tid >> 5;
    const int lane = tid & 31;
    const int w    = blockIdx.x;
    const int h    = blockIdx.y;

    uint32_t sraw  = smem_u32(asm_raw);
    uint32_t sb    = (sraw + 127u) & ~127u;
    uint8_t* smem  = asm_raw + (sb - sraw);

    // ---- load pre-split fp16 qkv into tiles ----
    for (int idx = tid; idx < 64 * 8; idx += 128) {
        const int i = idx >> 3, c4 = idx & 7, d0 = c4 * 4;
        if (i < NTOK) {
            const size_t rb = (size_t)(w * NTOK + i) * DIM + h * HEADD + d0;
            uint2 qh = *(const uint2*)&g_qh[rb];
            uint2 ql = *(const uint2*)&g_ql[rb];
            uint2 kh = *(const uint2*)&g_kh[rb];
            uint2 kl = *(const uint2*)&g_kl[rb];
            uint2 vh = *(const uint2*)&g_vh[rb];
            *(uint2*)(smem + tile_addr(A_QA1, i, d0))      = qh;
            *(uint2*)(smem + tile_addr(A_QA1, i, d0 + 32)) = qh;
            *(uint2*)(smem + tile_addr(A_QA2, i, d0))      = ql;
            *(uint2*)(smem + tile_addr(A_QA2, i, d0 + 32)) = ql;
            *(uint2*)(smem + tile_addr(A_KB,  i, d0))      = kh;
            *(uint2*)(smem + tile_addr(A_KB,  i, d0 + 32)) = kl;
            const __half* vhp = (const __half*)&vh;
            #pragma unroll
            for (int m = 0; m < 4; m++)
                *(__half*)(smem + tile_addr(A_VT, d0 + m, i)) = vhp[m];
        } else {
            #pragma unroll
            for (int m = 0; m < 4; m++)
                *(__half*)(smem + tile_addr(A_VT, d0 + m, i)) = __half(0);
        }
    }
    __syncthreads();   // the only block-wide barrier

    const int l15 = lane & 15;
    const int lhi = lane >> 4;
    const int g8  = lane >> 3;
    const int l8  = lane & 7;

    // ---- QK^T: ks-outer, KB fragments loaded once per ks, both QA passes ----
    float sacc[8][4];
    #pragma unroll
    for (int nf = 0; nf < 8; nf++)
        #pragma unroll
        for (int e = 0; e < 4; e++) sacc[nf][e] = 0.0f;
    {
        const int rA = warp * 16 + l15;
        int rB[4];
        #pragma unroll
        for (int p = 0; p < 4; p++) rB[p] = p * 16 + (g8 >> 1) * 8 + l8;

        #pragma unroll
        for (int ks = 0; ks < 4; ks++) {
            const int c16a = ks * 2 + lhi;
            const uint32_t aoff = rA * 128 + ((c16a ^ (rA & 7)) << 4);
            uint32_t af1[4], af2[4];
            ldsm_x4(af1, sb + A_QA1 + aoff);
            ldsm_x4(af2, sb + A_QA2 + aoff);
            uint32_t bf[4][4];
            #pragma unroll
            for (int p = 0; p < 4; p++) {
                const int c16b = ks * 2 + (g8 & 1);
                ldsm_x4(bf[p], sb + A_KB + rB[p] * 128 +
                               ((c16b ^ (rB[p] & 7)) << 4));
            }
            #pragma unroll
            for (int p = 0; p < 4; p++) {
                mma16816(sacc[2 * p],     af1, &bf[p][0]);
                mma16816(sacc[2 * p + 1], af1, &bf[p][2]);
                mma16816(sacc[2 * p],     af2, &bf[p][0]);
                mma16816(sacc[2 * p + 1], af2, &bf[p][2]);
            }
        }
    }

    // ---- exp on registers + P store (hi only), guarded to rows < 49 ----
    const int r0 = warp * 16 + (lane >> 2);
    const int r1 = r0 + 8;
    const int cb = 2 * (lane & 3);
    float rsum0 = 0.0f, rsum1 = 0.0f;
    {
        const float* bm = g_bm +
            (size_t)((w & (NW_IMG - 1)) * NHEAD + h) * BM_SLICE;
        const bool gr0 = (r0 < NTOK);
        const bool gr1 = (r1 < NTOK);
        #pragma unroll
        for (int nf = 0; nf < 8; nf++) {
            const int c = nf * 8 + cb;
            if (gr0) {
                float2 bm0 = *(const float2*)(bm + r0 * BM_STRIDE + c);
                float e00 = 0.0f, e01 = 0.0f;
                if (c < NTOK) {
                    e00 = fast_exp(sacc[nf][0] + bm0.x - EXP_SHIFT);
                    if (c + 1 < NTOK)
                        e01 = fast_exp(sacc[nf][1] + bm0.y - EXP_SHIFT);
                }
                rsum0 += e00 + e01;
                *(__half2*)(smem + tile_addr(A_PH, r0, c)) =
                    __halves2half2(__float2half_rn(e00), __float2half_rn(e01));
            }
            if (gr1) {
                float2 bm1 = *(const float2*)(bm + r1 * BM_STRIDE + c);
                float e10 = 0.0f, e11 = 0.0f;
                if (c < NTOK) {
                    e10 = fast_exp(sacc[nf][2] + bm1.x - EXP_SHIFT);
                    if (c + 1 < NTOK)
                        e11 = fast_exp(sacc[nf][3] + bm1.y - EXP_SHIFT);
                }
                rsum1 += e10 + e11;
                *(__half2*)(smem + tile_addr(A_PH, r1, c)) =
                    __halves2half2(__float2half_rn(e10), __float2half_rn(e11));
            }
        }
    }
    rsum0 += __shfl_xor_sync(0xFFFFFFFF, rsum0, 1);
    rsum0 += __shfl_xor_sync(0xFFFFFFFF, rsum0, 2);
    rsum1 += __shfl_xor_sync(0xFFFFFFFF, rsum1, 1);
    rsum1 += __shfl_xor_sync(0xFFFFFFFF, rsum1, 2);
    const float rs0 = 1.0f / rsum0;
    const float rs1 = 1.0f / rsum1;
    __syncwarp();

    // ---- AV: PH @ VT -> O ----
    float oacc[4][4];
    #pragma unroll
    for (int nf = 0; nf < 4; nf++)
        #pragma unroll
        for (int e = 0; e < 4; e++) oacc[nf][e] = 0.0f;
    {
        const int rA = warp * 16 + l15;
        int rB[2];
        #pragma unroll
        for (int p = 0; p < 2; p++) rB[p] = p * 16 + (g8 >> 1) * 8 + l8;

        #pragma unroll
        for (int ks = 0; ks < 4; ks++) {
            uint32_t af[4];
            const int c16a = ks * 2 + lhi;
            ldsm_x4(af, sb + A_PH + rA * 128 + ((c16a ^ (rA & 7)) << 4));
            uint32_t bf[2][4];
            #pragma unroll
            for (int p = 0; p < 2; p++) {
                const int c16b = ks * 2 + (g8 & 1);
                ldsm_x4(bf[p], sb + A_VT + rB[p] * 128 +
                               ((c16b ^ (rB[p] & 7)) << 4));
            }
            mma16816(oacc[0], af, &bf[0][0]);
            mma16816(oacc[1], af, &bf[0][2]);
            mma16816(oacc[2], af, &bf[1][0]);
            mma16816(oacc[3], af, &bf[1][2]);
        }
    }

    // ---- epilogue: scale by register rowsums, fp16 hi-only store ----
    {
        #pragma unroll
        for (int hf = 0; hf < 2; hf++) {
            const int row = hf ? r1 : r0;
            const float rs = hf ? rs1 : rs0;
            if (row < NTOK) {
                __half* gp = g_attn2 + (size_t)(w * NTOK + row) * KG + h * HEADD;
                #pragma unroll
                for (int nf = 0; nf < 4; nf++) {
                    const int d = nf * 8 + cb;
                    *(__half2*)(gp + d) = __halves2half2(
                        __float2half_rn(oacc[nf][hf * 2 + 0] * rs),
                        __float2half_rn(oacc[nf][hf * 2 + 1] * rs));
                }
            }
        }
    }
}

// ---------------------------------------------------------------------------
// Launch: prep_all(1), bm_prep(2), gemm1(3, mode 1), attn(4), gemm3(5, mode 0)
// ---------------------------------------------------------------------------
extern "C" void kernel_launch(void* const* d_in, const int* in_sizes, int n_in,
                              void* d_out, int out_size)
{
    const float* x         = (const float*)d_in[0];
    const float* mask      = (const float*)d_in[1];
    const float* rel_table = (const float*)d_in[2];
    const float* qkv_w     = (const float*)d_in[3];
    const float* qkv_b     = (const float*)d_in[4];
    const float* proj_w    = (const float*)d_in[5];
    const float* proj_b    = (const float*)d_in[6];
    const int*   rel_idx   = (const int*)d_in[7];
    float*       out       = (float*)d_out;

    void *x2_p, *attn2_p, *wq2_p, *wp2_p;
    cudaGetSymbolAddress(&x2_p,    g_x2);
    cudaGetSymbolAddress(&attn2_p, g_attn2);
    cudaGetSymbolAddress(&wq2_p,   g_wqkv2);
    cudaGetSymbolAddress(&wp2_p,   g_wproj2);

    cudaFuncSetAttribute(gemm_mma,
                         cudaFuncAttributeMaxDynamicSharedMemorySize, GSMEM);
    cudaFuncSetAttribute(attn_tc_kernel,
                         cudaFuncAttributeMaxDynamicSharedMemorySize, ASMEM);

    // 1) fp16 conversions
    {
        long t4x  = (long)MROWS * (DIM / 4);
        long t4wq = (long)QKV_COLS * (DIM / 4);
        long t4wp = (long)DIM * (DIM / 4);
        long tot  = t4x + t4wq + t4wp;
        prep_all<<<(unsigned)((tot + 255) / 256), 256>>>(
            x, qkv_w, proj_w,
            (__half*)x2_p, (__half*)wq2_p, (__half*)wp2_p,
            t4x, t4wq, t4wp);
    }
    // 2) bias+mask combine
    {
        long tot = (long)NW_IMG * NHEAD * NTOK * NTOK;
        bm_prep_kernel<<<(unsigned)((tot + 255) / 256), 256>>>(
            rel_table, rel_idx, mask);
    }
    // 3) QKV GEMM -> pre-split fp16 q/k/v
    {
        dim3 grid(QKV_COLS / 128, MROWS / 128);
        gemm_mma<<<grid, 256, GSMEM>>>(
            (const __half*)x2_p, (const __half*)wq2_p,
            qkv_b, (float*)nullptr, QKV_COLS, 1);
    }
    // 4) tensor-core attention
    {
        dim3 grid(NWIN, NHEAD);
        attn_tc_kernel<<<grid, 128, ASMEM>>>();
    }
    // 5) projection GEMM -> out (fp32)
    {
        dim3 grid(DIM / 128, MROWS / 128);
        gemm_mma<<<grid, 256, GSMEM>>>(
            (const __half*)attn2_p, (const __half*)wp2_p,
            proj_b, out, DIM, 0);
    }
}

// round 17
// speedup vs baseline: 1.0615x; 1.0615x over previous
#include <cuda_runtime.h>
#include <cuda_fp16.h>
#include <cstdint>
#include <cstddef>

// ---------------------------------------------------------------------------
// WindowAttention (Swin) on GB300 — Round 17.
// R15 base (best: 2419us). Attention deltas only:
//   - exp phase guarded to real rows (<49)  [numerically validated in R16]
//   - 2 heads per block (256 thr, two tile sets, same warps/SM)
// GEMMs / prep / bm: R15 verbatim.
// ---------------------------------------------------------------------------

#define NWIN      8192
#define NTOK      49
#define DIM       384
#define NHEAD     12
#define HEADD     32
#define NW_IMG    64
#define MROWS     (NWIN * NTOK)        // 401408
#define QKV_COLS  1152
#define KG        384                  // GEMM K (plain fp16)
#define SCALE_F   0.17677669529663687f
#define EXP_SHIFT 5.545177444479562f   // 8*ln2 headroom for fp16 P
#define BM_STRIDE 50
#define BM_SLICE  3200                 // 64 rows * 50

// Device scratch
__device__ float  g_qkv[(size_t)MROWS * QKV_COLS];
__device__ __half g_x2[(size_t)MROWS * KG];
__device__ __half g_attn2[(size_t)MROWS * KG];
__device__ __half g_wqkv2[(size_t)QKV_COLS * KG];
__device__ __half g_wproj2[(size_t)DIM * KG];
__device__ float  g_bm[(size_t)NW_IMG * NHEAD * BM_SLICE];

// ---------------------------------------------------------------------------
// Helpers
// ---------------------------------------------------------------------------
__device__ __forceinline__ uint32_t smem_u32(const void* p) {
    uint32_t a;
    asm("{ .reg .u64 t; cvta.to.shared.u64 t, %1; cvt.u32.u64 %0, t; }"
        : "=r"(a) : "l"(p));
    return a;
}

__device__ __forceinline__ void cpa16(uint32_t dst, const void* src) {
    asm volatile("cp.async.cg.shared.global [%0], [%1], 16;"
                 :: "r"(dst), "l"(src));
}

__device__ __forceinline__ void ldsm_x4(uint32_t* r, uint32_t addr) {
    asm volatile("ldmatrix.sync.aligned.m8n8.x4.shared.b16 {%0,%1,%2,%3}, [%4];"
                 : "=r"(r[0]), "=r"(r[1]), "=r"(r[2]), "=r"(r[3])
                 : "r"(addr));
}

__device__ __forceinline__ void mma16816(float* d, const uint32_t* a,
                                         const uint32_t* b) {
    asm volatile(
        "mma.sync.aligned.m16n8k16.row.col.f32.f16.f16.f32 "
        "{%0,%1,%2,%3}, {%4,%5,%6,%7}, {%8,%9}, {%0,%1,%2,%3};"
        : "+f"(d[0]), "+f"(d[1]), "+f"(d[2]), "+f"(d[3])
        : "r"(a[0]), "r"(a[1]), "r"(a[2]), "r"(a[3]),
          "r"(b[0]), "r"(b[1]));
}

// exp(x) on the FMA pipe: 2^(x*log2e), deg-5 poly, rel err ~2.4e-6.
__device__ __forceinline__ float fast_exp(float x) {
    float t = fmaxf(x, -80.0f) * 1.442695040888963f;
    float r = rintf(t);
    float f = t - r;
    float p =             1.3333558e-3f;
    p = fmaf(p, f, 9.6181291e-3f);
    p = fmaf(p, f, 5.5504109e-2f);
    p = fmaf(p, f, 2.4022651e-1f);
    p = fmaf(p, f, 6.9314718e-1f);
    p = fmaf(p, f, 1.0f);
    int ri = (int)r;
    return __int_as_float(__float_as_int(p) + ri * 8388608);
}

// ---------------------------------------------------------------------------
// Prep kernel: fp32 [rows][384] -> fp16 [rows][384] for x, qkv_w, proj_w.
// ---------------------------------------------------------------------------
__global__ void prep_all(const float* __restrict__ x,
                         const float* __restrict__ qkv_w,
                         const float* __restrict__ proj_w,
                         __half* __restrict__ x2,
                         __half* __restrict__ wq2,
                         __half* __restrict__ wp2,
                         long t4x, long t4wq, long t4wp)
{
    long idx = (long)blockIdx.x * blockDim.x + threadIdx.x;
    const float* in;
    __half* out;
    if (idx < t4x)                    { in = x;      out = x2; }
    else if (idx < t4x + t4wq)        { idx -= t4x;  in = qkv_w; out = wq2; }
    else if (idx < t4x + t4wq + t4wp) { idx -= t4x + t4wq; in = proj_w; out = wp2; }
    else return;

    float4 v = *((const float4*)in + idx);
    __half2* o = (__half2*)out + idx * 2;
    o[0] = __halves2half2(__float2half_rn(v.x), __float2half_rn(v.y));
    o[1] = __halves2half2(__float2half_rn(v.z), __float2half_rn(v.w));
}

// bias+mask combine
__global__ void bm_prep_kernel(const float* __restrict__ rel_table,
                               const int* __restrict__ rel_idx,
                               const float* __restrict__ mask)
{
    long t = (long)blockIdx.x * blockDim.x + threadIdx.x;
    if (t >= (long)NW_IMG * NHEAD * NTOK * NTOK) return;
    int slice = (int)(t / (NTOK * NTOK));
    int idx   = (int)(t - (long)slice * (NTOK * NTOK));
    int wm    = slice / NHEAD;
    int h     = slice - wm * NHEAD;
    int i     = idx / NTOK;
    int j     = idx - i * NTOK;
    g_bm[(size_t)slice * BM_SLICE + i * BM_STRIDE + j] =
        rel_table[rel_idx[idx] * NHEAD + h] + mask[(size_t)wm * (NTOK * NTOK) + idx];
}

// ---------------------------------------------------------------------------
// HMMA GEMM (R15 verbatim, K=384)
// ---------------------------------------------------------------------------
#define BKC       64
#define NCH       (KG / BKC)            // 6
#define TILE_BYTES 16384
#define STAGE_BYTES (2 * TILE_BYTES)
#define GSMEM     (2 * STAGE_BYTES + 128)

__global__ __launch_bounds__(256, 2)
void gemm_mma(const __half* __restrict__ A,
              const __half* __restrict__ B,
              const float* __restrict__ bias,
              float* __restrict__ C, int Nn)
{
    extern __shared__ uint8_t smem_raw[];
    const int tid  = threadIdx.x;
    const int warp = tid >> 5;
    const int lane = tid & 31;

    uint32_t sraw  = smem_u32(smem_raw);
    uint32_t sbase = (sraw + 127u) & ~127u;

    const int m0 = blockIdx.y << 7;
    const int n0 = blockIdx.x << 7;

    const char* Ag = (const char*)(A + (size_t)m0 * KG);
    const char* Bg = (const char*)(B + (size_t)n0 * KG);
    uint32_t sw[4];
    size_t   go[4];
    #pragma unroll
    for (int i = 0; i < 4; i++) {
        int u = i * 256 + tid;
        int r = u >> 3, c = u & 7;
        sw[i] = (uint32_t)(r * 128 + ((c ^ (r & 7)) << 4));
        go[i] = (size_t)r * (KG * 2) + (size_t)c * 16;
    }

    auto load_chunk = [&](int c, int s) {
        uint32_t ab = sbase + s * STAGE_BYTES;
        uint32_t bb = ab + TILE_BYTES;
        size_t koff = (size_t)c * 128;
        #pragma unroll
        for (int i = 0; i < 4; i++) {
            cpa16(ab + sw[i], Ag + go[i] + koff);
            cpa16(bb + sw[i], Bg + go[i] + koff);
        }
        asm volatile("cp.async.commit_group;" ::: "memory");
    };

    const int wm = warp & 1;
    const int wn = warp >> 1;
    const int l15 = lane & 15;
    const int lhi = lane >> 4;
    const int g8  = lane >> 3;
    const int l8  = lane & 7;

    int rA[4], rowOffA[4];
    #pragma unroll
    for (int mf = 0; mf < 4; mf++) {
        rA[mf] = wm * 64 + mf * 16 + l15;
        rowOffA[mf] = rA[mf] * 128;
    }
    int rB[2], rowOffB[2];
    #pragma unroll
    for (int p = 0; p < 2; p++) {
        rB[p] = wn * 32 + p * 16 + (g8 >> 1) * 8 + l8;
        rowOffB[p] = rB[p] * 128;
    }

    float acc[4][4][4];
    #pragma unroll
    for (int mf = 0; mf < 4; mf++)
        #pragma unroll
        for (int nf = 0; nf < 4; nf++)
            #pragma unroll
            for (int e = 0; e < 4; e++) acc[mf][nf][e] = 0.0f;

    load_chunk(0, 0);

    for (int c = 0; c < NCH; ++c) {
        if (c + 1 < NCH) {
            load_chunk(c + 1, (c + 1) & 1);
            asm volatile("cp.async.wait_group 1;" ::: "memory");
        } else {
            asm volatile("cp.async.wait_group 0;" ::: "memory");
        }
        __syncthreads();

        const uint32_t aT = sbase + (c & 1) * STAGE_BYTES;
        const uint32_t bT = aT + TILE_BYTES;

        #pragma unroll
        for (int ks = 0; ks < 4; ++ks) {
            uint32_t af[4][4];
            #pragma unroll
            for (int mf = 0; mf < 4; mf++) {
                const int c16 = ks * 2 + lhi;
                ldsm_x4(af[mf], aT + rowOffA[mf] +
                                ((c16 ^ (rA[mf] & 7)) << 4));
            }
            uint32_t bf[2][4];
            #pragma unroll
            for (int p = 0; p < 2; p++) {
                const int c16 = ks * 2 + (g8 & 1);
                ldsm_x4(bf[p], bT + rowOffB[p] +
                               ((c16 ^ (rB[p] & 7)) << 4));
            }
            #pragma unroll
            for (int mf = 0; mf < 4; mf++) {
                mma16816(acc[mf][0], af[mf], &bf[0][0]);
                mma16816(acc[mf][1], af[mf], &bf[0][2]);
                mma16816(acc[mf][2], af[mf], &bf[1][0]);
                mma16816(acc[mf][3], af[mf], &bf[1][2]);
            }
        }
        __syncthreads();
    }

    const int colBase = n0 + wn * 32 + 2 * (lane & 3);
    float2 b2[4];
    #pragma unroll
    for (int nf = 0; nf < 4; nf++)
        b2[nf] = *(const float2*)(bias + colBase + nf * 8);

    const int rowBase = m0 + wm * 64 + (lane >> 2);
    #pragma unroll
    for (int mf = 0; mf < 4; mf++) {
        const int r0 = rowBase + mf * 16;
        #pragma unroll
        for (int nf = 0; nf < 4; nf++) {
            const int col = colBase + nf * 8;
            float2 v0 = make_float2(acc[mf][nf][0] + b2[nf].x,
                                    acc[mf][nf][1] + b2[nf].y);
            float2 v1 = make_float2(acc[mf][nf][2] + b2[nf].x,
                                    acc[mf][nf][3] + b2[nf].y);
            *(float2*)(C + (size_t)r0 * Nn + col)       = v0;
            *(float2*)(C + (size_t)(r0 + 8) * Nn + col) = v1;
        }
    }
}

// ---------------------------------------------------------------------------
// Tensor-core attention: grid (NWIN, NHEAD/2), 256 threads (2 heads/block).
// Each 128-thread group handles one head with its own 36KB tile set.
// Exp phase guarded to rows < 49.
// ---------------------------------------------------------------------------
#define A_QA1 0
#define A_QA2 8192
#define A_KB  16384
#define A_PH  24576
#define A_VT  32768
#define HSET  36864
#define ASMEM (2 * HSET + 128)

__device__ __forceinline__ uint32_t tile_addr(uint32_t tile, int row, int j) {
    return tile + row * 128 + ((((j >> 3) ^ (row & 7)) << 4) | ((j & 7) * 2));
}

__global__ __launch_bounds__(256)
void attn_tc_kernel()
{
    extern __shared__ uint8_t asm_raw[];
    const int tid    = threadIdx.x;
    const int grp    = tid >> 7;            // head sub-block (0/1)
    const int wg_tid = tid & 127;
    const int warp4  = (tid >> 5) & 3;      // warp within head group
    const int lane   = tid & 31;
    const int w      = blockIdx.x;
    const int h      = blockIdx.y * 2 + grp;

    uint32_t sraw = smem_u32(asm_raw);
    uint32_t sb0  = (sraw + 127u) & ~127u;
    const uint32_t sb = sb0 + grp * HSET;
    uint8_t* smem = asm_raw + (sb - sraw);

    // ---- load qkv (fp32), build fp16 tiles (VT zero-padded, i to 64) ----
    const size_t base0 = (size_t)w * NTOK * QKV_COLS + h * HEADD;
    for (int idx = wg_tid; idx < 64 * 8; idx += 128) {
        const int i = idx >> 3, c4 = idx & 7, d0 = c4 * 4;
        if (i < NTOK) {
            const float* gp = g_qkv + base0 + (size_t)i * QKV_COLS + d0;
            float4 qv = *(const float4*)gp;
            float4 kv = *(const float4*)(gp + 384);
            float4 vv = *(const float4*)(gp + 768);
            float qa[4] = {qv.x * SCALE_F, qv.y * SCALE_F,
                           qv.z * SCALE_F, qv.w * SCALE_F};
            float ka[4] = {kv.x, kv.y, kv.z, kv.w};
            float va[4] = {vv.x, vv.y, vv.z, vv.w};
            __half qh[4], ql[4], kh[4], kl[4];
            #pragma unroll
            for (int m = 0; m < 4; m++) {
                qh[m] = __float2half_rn(qa[m]);
                ql[m] = __float2half_rn(qa[m] - __half2float(qh[m]));
                kh[m] = __float2half_rn(ka[m]);
                kl[m] = __float2half_rn(ka[m] - __half2float(kh[m]));
            }
            uint32_t qhp[2] = {((uint32_t*)qh)[0], ((uint32_t*)qh)[1]};
            uint32_t qlp[2] = {((uint32_t*)ql)[0], ((uint32_t*)ql)[1]};
            uint32_t khp[2] = {((uint32_t*)kh)[0], ((uint32_t*)kh)[1]};
            uint32_t klp[2] = {((uint32_t*)kl)[0], ((uint32_t*)kl)[1]};
            *(uint2*)(smem + tile_addr(A_QA1, i, d0))      = make_uint2(qhp[0], qhp[1]);
            *(uint2*)(smem + tile_addr(A_QA1, i, d0 + 32)) = make_uint2(qhp[0], qhp[1]);
            *(uint2*)(smem + tile_addr(A_QA2, i, d0))      = make_uint2(qlp[0], qlp[1]);
            *(uint2*)(smem + tile_addr(A_QA2, i, d0 + 32)) = make_uint2(qlp[0], qlp[1]);
            *(uint2*)(smem + tile_addr(A_KB,  i, d0))      = make_uint2(khp[0], khp[1]);
            *(uint2*)(smem + tile_addr(A_KB,  i, d0 + 32)) = make_uint2(klp[0], klp[1]);
            #pragma unroll
            for (int m = 0; m < 4; m++)
                *(__half*)(smem + tile_addr(A_VT, d0 + m, i)) =
                    __float2half_rn(va[m]);
        } else {
            #pragma unroll
            for (int m = 0; m < 4; m++)
                *(__half*)(smem + tile_addr(A_VT, d0 + m, i)) = __half(0);
        }
    }
    __syncthreads();   // the only block-wide barrier

    const int l15 = lane & 15;
    const int lhi = lane >> 4;
    const int g8  = lane >> 3;
    const int l8  = lane & 7;

    // ---- QK^T: ks-outer, KB fragments loaded once per ks, both QA passes ----
    float sacc[8][4];
    #pragma unroll
    for (int nf = 0; nf < 8; nf++)
        #pragma unroll
        for (int e = 0; e < 4; e++) sacc[nf][e] = 0.0f;
    {
        const int rA = warp4 * 16 + l15;
        int rB[4];
        #pragma unroll
        for (int p = 0; p < 4; p++) rB[p] = p * 16 + (g8 >> 1) * 8 + l8;

        #pragma unroll
        for (int ks = 0; ks < 4; ks++) {
            const int c16a = ks * 2 + lhi;
            const uint32_t aoff = rA * 128 + ((c16a ^ (rA & 7)) << 4);
            uint32_t af1[4], af2[4];
            ldsm_x4(af1, sb + A_QA1 + aoff);
            ldsm_x4(af2, sb + A_QA2 + aoff);
            uint32_t bf[4][4];
            #pragma unroll
            for (int p = 0; p < 4; p++) {
                const int c16b = ks * 2 + (g8 & 1);
                ldsm_x4(bf[p], sb + A_KB + rB[p] * 128 +
                               ((c16b ^ (rB[p] & 7)) << 4));
            }
            #pragma unroll
            for (int p = 0; p < 4; p++) {
                mma16816(sacc[2 * p],     af1, &bf[p][0]);
                mma16816(sacc[2 * p + 1], af1, &bf[p][2]);
                mma16816(sacc[2 * p],     af2, &bf[p][0]);
                mma16816(sacc[2 * p + 1], af2, &bf[p][2]);
            }
        }
    }

    // ---- exp on registers + P store (hi only), guarded to rows < 49 ----
    const int r0 = warp4 * 16 + (lane >> 2);
    const int r1 = r0 + 8;
    const int cb = 2 * (lane & 3);
    float rsum0 = 0.0f, rsum1 = 0.0f;
    {
        const float* bm = g_bm +
            (size_t)((w & (NW_IMG - 1)) * NHEAD + h) * BM_SLICE;
        const bool gr0 = (r0 < NTOK);
        const bool gr1 = (r1 < NTOK);
        #pragma unroll
        for (int nf = 0; nf < 8; nf++) {
            const int c = nf * 8 + cb;
            if (gr0) {
                float2 bm0 = *(const float2*)(bm + r0 * BM_STRIDE + c);
                float e00 = 0.0f, e01 = 0.0f;
                if (c < NTOK) {
                    e00 = fast_exp(sacc[nf][0] + bm0.x - EXP_SHIFT);
                    if (c + 1 < NTOK)
                        e01 = fast_exp(sacc[nf][1] + bm0.y - EXP_SHIFT);
                }
                rsum0 += e00 + e01;
                *(__half2*)(smem + tile_addr(A_PH, r0, c)) =
                    __halves2half2(__float2half_rn(e00), __float2half_rn(e01));
            }
            if (gr1) {
                float2 bm1 = *(const float2*)(bm + r1 * BM_STRIDE + c);
                float e10 = 0.0f, e11 = 0.0f;
                if (c < NTOK) {
                    e10 = fast_exp(sacc[nf][2] + bm1.x - EXP_SHIFT);
                    if (c + 1 < NTOK)
                        e11 = fast_exp(sacc[nf][3] + bm1.y - EXP_SHIFT);
                }
                rsum1 += e10 + e11;
                *(__half2*)(smem + tile_addr(A_PH, r1, c)) =
                    __halves2half2(__float2half_rn(e10), __float2half_rn(e11));
            }
        }
    }
    rsum0 += __shfl_xor_sync(0xFFFFFFFF, rsum0, 1);
    rsum0 += __shfl_xor_sync(0xFFFFFFFF, rsum0, 2);
    rsum1 += __shfl_xor_sync(0xFFFFFFFF, rsum1, 1);
    rsum1 += __shfl_xor_sync(0xFFFFFFFF, rsum1, 2);
    const float rs0 = 1.0f / rsum0;
    const float rs1 = 1.0f / rsum1;
    __syncwarp();

    // ---- AV: PH @ VT -> O ----
    float oacc[4][4];
    #pragma unroll
    for (int nf = 0; nf < 4; nf++)
        #pragma unroll
        for (int e = 0; e < 4; e++) oacc[nf][e] = 0.0f;
    {
        const int rA = warp4 * 16 + l15;
        int rB[2];
        #pragma unroll
        for (int p = 0; p < 2; p++) rB[p] = p * 16 + (g8 >> 1) * 8 + l8;

        #pragma unroll
        for (int ks = 0; ks < 4; ks++) {
            uint32_t af[4];
            const int c16a = ks * 2 + lhi;
            ldsm_x4(af, sb + A_PH + rA * 128 + ((c16a ^ (rA & 7)) << 4));
            uint32_t bf[2][4];
            #pragma unroll
            for (int p = 0; p < 2; p++) {
                const int c16b = ks * 2 + (g8 & 1);
                ldsm_x4(bf[p], sb + A_VT + rB[p] * 128 +
                               ((c16b ^ (rB[p] & 7)) << 4));
            }
            mma16816(oacc[0], af, &bf[0][0]);
            mma16816(oacc[1], af, &bf[0][2]);
            mma16816(oacc[2], af, &bf[1][0]);
            mma16816(oacc[3], af, &bf[1][2]);
        }
    }

    // ---- epilogue: scale by register rowsums, fp16 hi-only store ----
    {
        #pragma unroll
        for (int hf = 0; hf < 2; hf++) {
            const int row = hf ? r1 : r0;
            const float rs = hf ? rs1 : rs0;
            if (row < NTOK) {
                __half* gp = g_attn2 + (size_t)(w * NTOK + row) * KG + h * HEADD;
                #pragma unroll
                for (int nf = 0; nf < 4; nf++) {
                    const int d = nf * 8 + cb;
                    *(__half2*)(gp + d) = __halves2half2(
                        __float2half_rn(oacc[nf][hf * 2 + 0] * rs),
                        __float2half_rn(oacc[nf][hf * 2 + 1] * rs));
                }
            }
        }
    }
}

// ---------------------------------------------------------------------------
// Launch: prep_all(1), bm_prep(2), gemm1(3), attn(4), gemm3(5)
// ---------------------------------------------------------------------------
extern "C" void kernel_launch(void* const* d_in, const int* in_sizes, int n_in,
                              void* d_out, int out_size)
{
    const float* x         = (const float*)d_in[0];
    const float* mask      = (const float*)d_in[1];
    const float* rel_table = (const float*)d_in[2];
    const float* qkv_w     = (const float*)d_in[3];
    const float* qkv_b     = (const float*)d_in[4];
    const float* proj_w    = (const float*)d_in[5];
    const float* proj_b    = (const float*)d_in[6];
    const int*   rel_idx   = (const int*)d_in[7];
    float*       out       = (float*)d_out;

    void *qkv_p, *x2_p, *attn2_p, *wq2_p, *wp2_p;
    cudaGetSymbolAddress(&qkv_p,   g_qkv);
    cudaGetSymbolAddress(&x2_p,    g_x2);
    cudaGetSymbolAddress(&attn2_p, g_attn2);
    cudaGetSymbolAddress(&wq2_p,   g_wqkv2);
    cudaGetSymbolAddress(&wp2_p,   g_wproj2);

    cudaFuncSetAttribute(gemm_mma,
                         cudaFuncAttributeMaxDynamicSharedMemorySize, GSMEM);
    cudaFuncSetAttribute(attn_tc_kernel,
                         cudaFuncAttributeMaxDynamicSharedMemorySize, ASMEM);

    // 1) fp16 conversions
    {
        long t4x  = (long)MROWS * (DIM / 4);
        long t4wq = (long)QKV_COLS * (DIM / 4);
        long t4wp = (long)DIM * (DIM / 4);
        long tot  = t4x + t4wq + t4wp;
        prep_all<<<(unsigned)((tot + 255) / 256), 256>>>(
            x, qkv_w, proj_w,
            (__half*)x2_p, (__half*)wq2_p, (__half*)wp2_p,
            t4x, t4wq, t4wp);
    }
    // 2) bias+mask combine
    {
        long tot = (long)NW_IMG * NHEAD * NTOK * NTOK;
        bm_prep_kernel<<<(unsigned)((tot + 255) / 256), 256>>>(
            rel_table, rel_idx, mask);
    }
    // 3) QKV GEMM (K=384) -> fp32 qkv
    {
        dim3 grid(QKV_COLS / 128, MROWS / 128);
        gemm_mma<<<grid, 256, GSMEM>>>(
            (const __half*)x2_p, (const __half*)wq2_p,
            qkv_b, (float*)qkv_p, QKV_COLS);
    }
    // 4) tensor-core attention (2 heads per block)
    {
        dim3 grid(NWIN, NHEAD / 2);
        attn_tc_kernel<<<grid, 256, ASMEM>>>();
    }
    // 5) projection GEMM (K=384)
    {
        dim3 grid(DIM / 128, MROWS / 128);
        gemm_mma<<<grid, 256, GSMEM>>>(
            (const __half*)attn2_p, (const __half*)wp2_p,
            proj_b, out, DIM);
    }
}